// round 13
// baseline (speedup 1.0000x reference)
#include <cuda_runtime.h>

#define Bn 1024
#define Cc 128
#define Dd 16
#define Ss 4
#define NK3 23
#define NK2 5
#define NK1 2
#define NM3 816   // # monomials, ordered by (j, i, l): m = off3[j] + i*(16-j) + (l-j)
#define NM2 136   // # pairs, ordered by (j, i): m = j(j+1)/2 + i
#define OT 4      // total output irrep components: 1 (0e) + 3 (1o)

typedef unsigned long long u64;

// ---------------- scratch (device globals; no allocation allowed) ----------------
__device__ float  g_u3s[OT*NM3*NK3 + 512]; // symmetrized u3, layout [o][m][k] (+pad)
__device__ float  g_u2s[OT*NK2*NM2];       // symmetrized u2, layout [o][k][m]
__device__ float4 g_uw3s[Ss*Cc*NM3];       // per-(species,channel) weighted basis, float4 over o
__device__ float4 g_uw2s[Ss*Cc*NM2];
__device__ float4 g_uw1s[Ss*Cc*Dd];
__device__ float  g_Y[OT*Cc*Bn];           // y[o][c][p]  (p = species-compact position)
__device__ int    g_count[Ss];
__device__ int    g_list[Ss*Bn];
__device__ int    g_pb[Bn];                // compact position -> node index
__device__ unsigned g_barc;                // grid barrier count (returns to 0 each run)
__device__ volatile unsigned g_bars;       // grid barrier sense (flips each run)

__device__ __forceinline__ float u3at(const float* __restrict__ u3_0,
                                      const float* __restrict__ u3_1,
                                      int o, int a, int b, int c, int k) {
    if (o == 0) return u3_0[((a*Dd + b)*Dd + c)*NK3 + k];
    return u3_1[((((o-1)*Dd + a)*Dd + b)*Dd + c)*NK3 + k];
}

// ---------------- fused prep+fold: 296 CTAs, 128-reg budget, grid barrier ----------------
// __launch_bounds__(256,2) => regs<=128, smem 29.4KB*2=59KB/SM => 2 CTAs/SM guaranteed
// => 296 slots >= 296 CTAs => ALL resident => barrier is deadlock-free & replay-safe.
#define PF_BLKS 296
#define F3_UNITS 208              // 4 species x 13 m-tiles(64) x 4 c-blocks(32)
#define F2_UNITS (Ss*Cc*NM2/256)  // 272
#define F1_UNITS (Ss*Cc*Dd/256)   // 32
#define TOT_UNITS (F3_UNITS + F2_UNITS + F1_UNITS)   // 512

__global__ void __launch_bounds__(256, 2) k_pf(
        const float* __restrict__ u3_0, const float* __restrict__ u3_1,
        const float* __restrict__ u2_0, const float* __restrict__ u2_1,
        const float* __restrict__ u1_0, const float* __restrict__ u1_1,
        const float* __restrict__ w3, const float* __restrict__ w2,
        const float* __restrict__ w1, const int* __restrict__ sp) {
    __shared__ float su[OT][NK3][64];   // 23.5 KB (fold3 tile)
    __shared__ float sw[2][NK3][32];    //  5.9 KB
    int blk = blockIdx.x;
    int t = threadIdx.x;

    // ===== PHASE A: blk0 = fast sort; blks 1..294 = sym3; blk295 = sym2 =====
    if (blk == 0) {
        // warp-aggregated counting sort: 1 atomic per warp per species
        if (t < Ss) g_count[t] = 0;
        __syncthreads();
        int lane = t & 31;
        for (int b = t; b < Bn; b += 256) {
            int e = sp[b];
            int pos = 0;
            #pragma unroll
            for (int q = 0; q < Ss; q++) {
                unsigned msk = __ballot_sync(0xffffffffu, e == q);
                if (e == q) {
                    int rank = __popc(msk & ((1u << lane) - 1));
                    int leader = __ffs(msk) - 1;
                    int base = 0;
                    if (lane == leader) base = atomicAdd(&g_count[q], __popc(msk));
                    base = __shfl_sync(msk, base, leader);
                    pos = base + rank;
                }
            }
            g_list[e*Bn + pos] = b;
        }
        __syncthreads();
        int off = 0;
        for (int e = 0; e < Ss; e++) {
            int n = g_count[e];
            for (int i = t; i < n; i += 256) g_pb[off + i] = g_list[e*Bn + i];
            off += n;
        }
    } else if (blk <= 294) {
        // sym3 -> g_u3s[o][m][k], thread per (o,m,k); equality-case perms
        int tid = (blk-1)*256 + t;
        if (tid < OT*NM3*NK3) {
            int k  = tid % NK3;
            int om = tid / NK3;
            int m  = om % NM3;
            int o  = om / NM3;
            const int off3[17] = {0,16,46,88,140,200,266,336,408,480,550,616,676,728,770,800,816};
            int j = 0;
            #pragma unroll
            for (int q = 1; q < 16; q++) if (m >= off3[q]) j = q;
            int r = m - off3[j];
            int w = 16 - j;
            int i = r / w;          // i <= j
            int l = j + r % w;      // l >= j
            float s = u3at(u3_0, u3_1, o, i, j, l, k);
            if (i < j && j < l) {
                s += u3at(u3_0, u3_1, o, i, l, j, k) + u3at(u3_0, u3_1, o, j, i, l, k)
                   + u3at(u3_0, u3_1, o, j, l, i, k) + u3at(u3_0, u3_1, o, l, i, j, k)
                   + u3at(u3_0, u3_1, o, l, j, i, k);
            } else if (i == j && j < l) {
                s += u3at(u3_0, u3_1, o, i, l, i, k) + u3at(u3_0, u3_1, o, l, i, i, k);
            } else if (i < j && j == l) {
                s += u3at(u3_0, u3_1, o, j, i, j, k) + u3at(u3_0, u3_1, o, j, j, i, k);
            }
            g_u3s[(o*NM3 + m)*NK3 + k] = s;
        }
    } else {
        // blk295: sym2 -> g_u2s[o][k][m], pair order (j,i)
        for (int tid = t; tid < OT*256; tid += 256) {
            int o = tid >> 8;
            int r = tid & 255;
            int i = (r >> 4) & 15, j = r & 15;
            if (i <= j) {
                int m = j*(j+1)/2 + i;
                for (int k = 0; k < NK2; k++) {
                    float s;
                    if (o == 0) {
                        s = u2_0[(i*Dd + j)*NK2 + k];
                        if (i != j) s += u2_0[(j*Dd + i)*NK2 + k];
                    } else {
                        s = u2_1[(((o-1)*Dd + i)*Dd + j)*NK2 + k];
                        if (i != j) s += u2_1[(((o-1)*Dd + j)*Dd + i)*NK2 + k];
                    }
                    g_u2s[(o*NK2 + k)*NM2 + m] = s;
                }
            }
        }
    }

    // ================= DEVICE-WIDE BARRIER (all 296 CTAs resident) =================
    __syncthreads();
    if (t == 0) {
        unsigned s = g_bars;
        __threadfence();                       // publish phase-A writes
        unsigned arr = atomicAdd(&g_barc, 1);
        if (arr == PF_BLKS - 1) {
            g_barc = 0;
            __threadfence();
            g_bars = s ^ 1u;                   // release
        } else {
            while (g_bars == s) { }            // volatile spin
        }
        __threadfence();                       // acquire
    }
    __syncthreads();

    // ================= PHASE B: fold units (<=2 per CTA) =================
    for (int u = blk; u < TOT_UNITS; u += PF_BLKS) {
        __syncthreads();                       // protect smem reuse across units
        if (u < F3_UNITS) {
            // fold3 (R7-proven body)
            int e  = u / 52;
            int r  = u % 52;
            int m0 = (r >> 2) * 64;
            int c0 = (r & 3) * 32;
            for (int idx = t; idx < OT*NK3*64; idx += 256) {
                int k = idx % NK3; int mo = idx / NK3; int m = mo & 63; int o = mo >> 6;
                su[o][k][m] = g_u3s[(o*NM3 + m0 + m)*NK3 + k];   // may over-read into pad
            }
            for (int idx = t; idx < 2*NK3*32; idx += 256) {
                int cw = idx & 31; int sk = idx >> 5; int k = sk % NK3; int s = sk / NK3;
                sw[s][k][cw] = w3[((s*Ss + e)*NK3 + k)*Cc + c0 + cw];
            }
            __syncthreads();
            int m = t & 63;
            int cq = t >> 6;
            bool valid = (m0 + m) < NM3;
            #pragma unroll
            for (int ci = 0; ci < 2; ci++) {
                int cl = cq*8 + ci*4;
                float s00=0,s01=0,s02=0,s03=0, s10=0,s11=0,s12=0,s13=0;
                float s20=0,s21=0,s22=0,s23=0, s30=0,s31=0,s32=0,s33=0;
                #pragma unroll
                for (int k = 0; k < NK3; k++) {
                    float u0 = su[0][k][m], u1 = su[1][k][m];
                    float u2 = su[2][k][m], u3 = su[3][k][m];
                    float4 wa = *reinterpret_cast<float4*>(&sw[0][k][cl]);
                    float4 wb = *reinterpret_cast<float4*>(&sw[1][k][cl]);
                    s00 += u0*wa.x; s01 += u1*wb.x; s02 += u2*wb.x; s03 += u3*wb.x;
                    s10 += u0*wa.y; s11 += u1*wb.y; s12 += u2*wb.y; s13 += u3*wb.y;
                    s20 += u0*wa.z; s21 += u1*wb.z; s22 += u2*wb.z; s23 += u3*wb.z;
                    s30 += u0*wa.w; s31 += u1*wb.w; s32 += u2*wb.w; s33 += u3*wb.w;
                }
                if (valid) {
                    int mm = m0 + m;
                    g_uw3s[(e*Cc + c0 + cl + 0)*NM3 + mm] = make_float4(s00,s01,s02,s03);
                    g_uw3s[(e*Cc + c0 + cl + 1)*NM3 + mm] = make_float4(s10,s11,s12,s13);
                    g_uw3s[(e*Cc + c0 + cl + 2)*NM3 + mm] = make_float4(s20,s21,s22,s23);
                    g_uw3s[(e*Cc + c0 + cl + 3)*NM3 + mm] = make_float4(s30,s31,s32,s33);
                }
            }
        } else if (u < F3_UNITS + F2_UNITS) {
            int tid = (u - F3_UNITS)*256 + t;
            int m = tid % NM2; int ec = tid / NM2;
            int c = ec % Cc;   int e  = ec / Cc;
            const float* w0  = w2 + ((0*Ss + e)*NK2)*Cc + c;
            const float* w1v = w2 + ((1*Ss + e)*NK2)*Cc + c;
            float s0=0.f, s1=0.f, s2=0.f, s3=0.f;
            #pragma unroll
            for (int k = 0; k < NK2; k++) {
                float a = __ldg(w0 + k*Cc), b = __ldg(w1v + k*Cc);   // warp-uniform
                s0 += g_u2s[(0*NK2 + k)*NM2 + m]*a;
                s1 += g_u2s[(1*NK2 + k)*NM2 + m]*b;
                s2 += g_u2s[(2*NK2 + k)*NM2 + m]*b;
                s3 += g_u2s[(3*NK2 + k)*NM2 + m]*b;
            }
            g_uw2s[tid] = make_float4(s0,s1,s2,s3);
        } else {
            int tid = (u - F3_UNITS - F2_UNITS)*256 + t;
            int i = tid % Dd; int ec = tid / Dd;
            int c = ec % Cc;  int e  = ec / Cc;
            float s[OT];
            #pragma unroll
            for (int o = 0; o < OT; o++) {
                int set = (o == 0) ? 0 : 1;
                float acc = 0.f;
                #pragma unroll
                for (int k = 0; k < NK1; k++) {
                    float uv = (o == 0) ? u1_0[i*NK1 + k]
                                        : u1_1[(((o-1)*Dd) + i)*NK1 + k];
                    acc += uv * w1[((set*Ss + e)*NK1 + k)*Cc + c];
                }
                s[o] = acc;
            }
            g_uw1s[tid] = make_float4(s[0], s[1], s[2], s[3]);
        }
    }
}

// ---------------- main symmetric-contraction kernel (R7-exact) ----------------
#define FMA2(acc, a, b) asm("fma.rn.f32x2 %0, %1, %2, %0;" : "+l"(acc) : "l"(a), "l"(b))
#define MUL2(d, a, b)   asm("mul.rn.f32x2 %0, %1, %2;" : "=l"(d) : "l"(a), "l"(b))

__global__ void __launch_bounds__(128) k_main(const float* __restrict__ nf) {
    __shared__ ulonglong2 su3[NM3];     // 13056 B
    __shared__ ulonglong2 su2[NM2];     //  2176 B
    __shared__ ulonglong2 su1[Dd];      //   256 B
    int c = blockIdx.x, e = blockIdx.y, half = blockIdx.z;
    int t = threadIdx.x;
    int ec = e*Cc + c;
    const ulonglong2* G3 = reinterpret_cast<const ulonglong2*>(g_uw3s) + ec*NM3;
    const ulonglong2* G2 = reinterpret_cast<const ulonglong2*>(g_uw2s) + ec*NM2;
    const ulonglong2* G1 = reinterpret_cast<const ulonglong2*>(g_uw1s) + ec*Dd;
    for (int idx = t; idx < NM3; idx += 128) su3[idx] = G3[idx];
    for (int idx = t; idx < NM2; idx += 128) su2[idx] = G2[idx];
    if (t < Dd) su1[t] = G1[t];
    __syncthreads();
    int n = g_count[e];
    int off = 0;
    for (int q = 0; q < Ss; q++) if (q < e) off += g_count[q];
    for (int base = half*128; base < n; base += 256) {
        int li = base + t;
        if (li >= n) continue;            // no barriers below: safe divergence
        int p = off + li;
        int b = g_pb[p];
        const float4* src = reinterpret_cast<const float4*>(nf + (b*Cc + c)*Dd);
        float4 v0 = src[0], v1 = src[1], v2 = src[2], v3 = src[3];
        float x[16] = {v0.x,v0.y,v0.z,v0.w, v1.x,v1.y,v1.z,v1.w,
                       v2.x,v2.y,v2.z,v2.w, v3.x,v3.y,v3.z,v3.w};
        u64 xd[16];                        // {x_i, x_i} packed
        #pragma unroll
        for (int i = 0; i < 16; i++) {
            unsigned xi = __float_as_uint(x[i]);
            asm("mov.b64 %0, {%1, %1};" : "=l"(xd[i]) : "r"(xi));
        }
        u64 acc01 = 0ull, acc23 = 0ull;    // {a0,a1}, {a2,a3}
        int m3 = 0, m2 = 0;
        #pragma unroll
        for (int j = 0; j < 16; j++) {     // unrolled: (16-j) known per copy
            u64 xj = xd[j];
            ulonglong2 u1r = su1[j];
            FMA2(acc01, u1r.x, xj);
            FMA2(acc23, u1r.y, xj);
            const int w = 16 - j;
            #pragma unroll 1
            for (int i = 0; i <= j; i++) { // rolled: keeps code small
                u64 xx; MUL2(xx, xd[i], xj);
                ulonglong2 u2r = su2[m2 + i];
                u64 d01 = u2r.x, d23 = u2r.y;    // dot = u2 + sum_l u3*x_l
                const ulonglong2* s3 = &su3[m3 + i*w];
                #pragma unroll
                for (int l = j; l < 16; l++) {
                    ulonglong2 u = s3[l - j];     // LDS.128 broadcast
                    FMA2(d01, u.x, xd[l]);
                    FMA2(d23, u.y, xd[l]);
                }
                FMA2(acc01, xx, d01);            // acc += xx * dot
                FMA2(acc23, xx, d23);
            }
            m2 += j + 1;
            m3 += (j + 1) * w;
        }
        unsigned r0, r1, r2, r3;
        asm("mov.b64 {%0,%1}, %2;" : "=r"(r0), "=r"(r1) : "l"(acc01));
        asm("mov.b64 {%0,%1}, %2;" : "=r"(r2), "=r"(r3) : "l"(acc23));
        g_Y[(0*Cc + c)*Bn + p] = __uint_as_float(r0);   // coalesced: p = off+base+t
        g_Y[(1*Cc + c)*Bn + p] = __uint_as_float(r1);
        g_Y[(2*Cc + c)*Bn + p] = __uint_as_float(r2);
        g_Y[(3*Cc + c)*Bn + p] = __uint_as_float(r3);
    }
}

// ---------------- final equivariant linear (R7-exact: one wave, 512 thr) ----------------
#define LIN_SMEM (Cc*Cc*4 + Cc*32*4)   // Ws 64KB + Ys 16KB = 81920 B
__global__ void __launch_bounds__(512) k_linear(const float* __restrict__ wlin,
                                                float* __restrict__ out) {
    extern __shared__ float sm[];
    float* Ws = sm;              // [128][128]
    float* Ys = sm + Cc*Cc;      // [128][32]
    int o  = blockIdx.y;
    int p0 = blockIdx.x * 32;
    int set = (o == 0) ? 0 : 1;
    int t  = threadIdx.x;
    const float4* wsrc = reinterpret_cast<const float4*>(wlin + set*Cc*Cc);
    float4* wdst = reinterpret_cast<float4*>(Ws);
    #pragma unroll
    for (int idx = t; idx < Cc*Cc/4; idx += 512) wdst[idx] = wsrc[idx];
    #pragma unroll
    for (int idx = t; idx < Cc*32; idx += 512) {
        int cc = idx >> 5, pp = idx & 31;
        Ys[cc*32 + pp] = g_Y[(o*Cc + cc)*Bn + p0 + pp];
    }
    __syncthreads();
    int tp = t & 15;          // 16 row-slots x 2 rows = 32
    int tn = t >> 4;          // 32 col-slots x 4 cols = 128
    float a0x=0,a0y=0,a0z=0,a0w=0, a1x=0,a1y=0,a1z=0,a1w=0;
    #pragma unroll 16
    for (int cc = 0; cc < Cc; cc++) {
        float2 y = *reinterpret_cast<const float2*>(&Ys[cc*32 + tp*2]);   // broadcast-dedup
        float4 w = *reinterpret_cast<const float4*>(&Ws[cc*Cc + tn*4]);   // broadcast-dedup
        a0x += y.x*w.x; a0y += y.x*w.y; a0z += y.x*w.z; a0w += y.x*w.w;
        a1x += y.y*w.x; a1y += y.y*w.y; a1z += y.y*w.z; a1w += y.y*w.w;
    }
    const float scale = 0.08838834764831845f;    // 1/sqrt(128)
    float4 r0 = make_float4(a0x*scale, a0y*scale, a0z*scale, a0w*scale);
    float4 r1 = make_float4(a1x*scale, a1y*scale, a1z*scale, a1w*scale);
    int p_a = p0 + tp*2;
    int b0 = g_pb[p_a + 0], b1 = g_pb[p_a + 1];
    if (o == 0) {
        *reinterpret_cast<float4*>(&out[b0*512 + tn*4]) = r0;
        *reinterpret_cast<float4*>(&out[b1*512 + tn*4]) = r1;
    } else {
        int op = o - 1;
        float* o0 = &out[b0*512 + 128 + op];
        float* o1 = &out[b1*512 + 128 + op];
        o0[(tn*4+0)*3] = r0.x; o0[(tn*4+1)*3] = r0.y; o0[(tn*4+2)*3] = r0.z; o0[(tn*4+3)*3] = r0.w;
        o1[(tn*4+0)*3] = r1.x; o1[(tn*4+1)*3] = r1.y; o1[(tn*4+2)*3] = r1.z; o1[(tn*4+3)*3] = r1.w;
    }
}

// ---------------- launch (3 launches) ----------------
extern "C" void kernel_launch(void* const* d_in, const int* in_sizes, int n_in,
                              void* d_out, int out_size) {
    const float* nf   = (const float*)d_in[0];
    const float* u3_0 = (const float*)d_in[1];
    const float* u3_1 = (const float*)d_in[2];
    const float* u2_0 = (const float*)d_in[3];
    const float* u2_1 = (const float*)d_in[4];
    const float* u1_0 = (const float*)d_in[5];
    const float* u1_1 = (const float*)d_in[6];
    const float* w3   = (const float*)d_in[7];
    const float* w2   = (const float*)d_in[8];
    const float* w1   = (const float*)d_in[9];
    const float* wl   = (const float*)d_in[10];
    const int*   sp   = (const int*)d_in[11];
    float* out = (float*)d_out;

    cudaFuncSetAttribute(k_linear, cudaFuncAttributeMaxDynamicSharedMemorySize, LIN_SMEM);

    k_pf<<<PF_BLKS, 256>>>(u3_0, u3_1, u2_0, u2_1, u1_0, u1_1, w3, w2, w1, sp);
    k_main<<<dim3(Cc, Ss, 2), 128>>>(nf);
    k_linear<<<dim3(Bn/32, 4), 512, LIN_SMEM>>>(wl, out);
}

// round 15
// speedup vs baseline: 1.0566x; 1.0566x over previous
#include <cuda_runtime.h>

#define Bn 1024
#define Cc 128
#define Dd 16
#define Ss 4
#define NK3 23
#define NK2 5
#define NK1 2
#define NM3 816   // # monomials, ordered by (j, i, l): m = off3[j] + i*(16-j) + (l-j)
#define NM2 136   // # pairs, ordered by (j, i): m = j(j+1)/2 + i
#define OT 4      // total output irrep components: 1 (0e) + 3 (1o)

typedef unsigned long long u64;

// ---------------- scratch (device globals; no allocation allowed) ----------------
__device__ float  g_u3s[OT*NM3*NK3 + 512]; // symmetrized u3, layout [o][m][k] (+pad)
__device__ float  g_u2s[OT*NK2*NM2];       // symmetrized u2, layout [o][k][m]
__device__ float4 g_uw3s[Ss*Cc*NM3];       // per-(species,channel) weighted basis, float4 over o
__device__ float4 g_uw2s[Ss*Cc*NM2];
__device__ float4 g_uw1s[Ss*Cc*Dd];
__device__ float  g_Y[OT*Cc*Bn];           // y[o][c][p]  (p = species-compact position)
__device__ int    g_count[Ss];
__device__ int    g_list[Ss*Bn];
__device__ int    g_pb[Bn];                // compact position -> node index

// ---------------- prep: species sort/compact + symmetrize u3/u2 (R7-exact) ----------------
__device__ __forceinline__ float u3at(const float* __restrict__ u3_0,
                                      const float* __restrict__ u3_1,
                                      int o, int a, int b, int c, int k) {
    if (o == 0) return u3_0[((a*Dd + b)*Dd + c)*NK3 + k];
    return u3_1[((((o-1)*Dd + a)*Dd + b)*Dd + c)*NK3 + k];
}

#define SYM3_BLKS 294
__global__ void k_prep(const int* __restrict__ sp,
                       const float* __restrict__ u3_0, const float* __restrict__ u3_1,
                       const float* __restrict__ u2_0, const float* __restrict__ u2_1) {
    int blk = blockIdx.x;
    int t = threadIdx.x;                 // 256 threads
    if (blk == 0) {
        // species counting-sort + compaction (single block so ordering is safe)
        if (t < Ss) g_count[t] = 0;
        __syncthreads();
        for (int b = t; b < Bn; b += 256) {
            int e = sp[b];
            int pos = atomicAdd(&g_count[e], 1);
            g_list[e*Bn + pos] = b;
        }
        __syncthreads();
        int off = 0;
        for (int e = 0; e < Ss; e++) {
            int n = g_count[e];
            for (int i = t; i < n; i += 256) g_pb[off + i] = g_list[e*Bn + i];
            off += n;
        }
    } else if (blk <= SYM3_BLKS) {
        // symmetrize u3 -> g_u3s[o][m][k], thread per (o,m,k); equality-case perms
        int tid = (blk-1)*256 + t;
        if (tid >= OT*NM3*NK3) return;
        int k  = tid % NK3;
        int om = tid / NK3;
        int m  = om % NM3;
        int o  = om / NM3;
        const int off3[17] = {0,16,46,88,140,200,266,336,408,480,550,616,676,728,770,800,816};
        int j = 0;
        #pragma unroll
        for (int q = 1; q < 16; q++) if (m >= off3[q]) j = q;
        int r = m - off3[j];
        int w = 16 - j;
        int i = r / w;          // i <= j
        int l = j + r % w;      // l >= j
        float s = u3at(u3_0, u3_1, o, i, j, l, k);
        if (i < j && j < l) {
            s += u3at(u3_0, u3_1, o, i, l, j, k) + u3at(u3_0, u3_1, o, j, i, l, k)
               + u3at(u3_0, u3_1, o, j, l, i, k) + u3at(u3_0, u3_1, o, l, i, j, k)
               + u3at(u3_0, u3_1, o, l, j, i, k);
        } else if (i == j && j < l) {
            s += u3at(u3_0, u3_1, o, i, l, i, k) + u3at(u3_0, u3_1, o, l, i, i, k);
        } else if (i < j && j == l) {
            s += u3at(u3_0, u3_1, o, j, i, j, k) + u3at(u3_0, u3_1, o, j, j, i, k);
        }
        g_u3s[(o*NM3 + m)*NK3 + k] = s;    // coalesced over k
    } else {
        // symmetrize u2 -> g_u2s[o][k][m], pair order (j,i)
        int tid = (blk-SYM3_BLKS-1)*256 + t;   // 0..1023 = 4 * 256
        if (tid >= OT*256) return;
        int o = tid >> 8;
        int r = tid & 255;
        int i = (r >> 4) & 15, j = r & 15;
        if (i > j) return;
        int m = j*(j+1)/2 + i;
        for (int k = 0; k < NK2; k++) {
            float s;
            if (o == 0) {
                s = u2_0[(i*Dd + j)*NK2 + k];
                if (i != j) s += u2_0[(j*Dd + i)*NK2 + k];
            } else {
                s = u2_1[(((o-1)*Dd + i)*Dd + j)*NK2 + k];
                if (i != j) s += u2_1[(((o-1)*Dd + j)*Dd + i)*NK2 + k];
            }
            g_u2s[(o*NK2 + k)*NM2 + m] = s;
        }
    }
}

// ---------------- fold: species weights into bases ----------------
// fold3: 416 CTAs = 4 species x 13 m-tiles(64) x 8 c-blocks(16)  [R14: was 208 x 32-col]
#define F3_BLKS 416
#define F2_BLKS (Ss*Cc*NM2/256)   // 272
#define F1_BLKS (Ss*Cc*Dd/256)    // 32

__global__ void __launch_bounds__(256) k_fold(
        const float* __restrict__ w3, const float* __restrict__ w2,
        const float* __restrict__ u1_0, const float* __restrict__ u1_1,
        const float* __restrict__ w1) {
    int blk = blockIdx.x;
    int t = threadIdx.x;
    if (blk < F3_BLKS) {
        __shared__ float su[OT][NK3][64];   // 23.5 KB
        __shared__ float sw[2][NK3][16];    //  2.9 KB
        int e  = blk / 104;
        int r  = blk % 104;
        int m0 = (r >> 3) * 64;
        int c0 = (r & 7) * 16;
        for (int idx = t; idx < OT*NK3*64; idx += 256) {
            int k = idx % NK3; int mo = idx / NK3; int m = mo & 63; int o = mo >> 6;
            su[o][k][m] = g_u3s[(o*NM3 + m0 + m)*NK3 + k];   // may over-read into pad
        }
        for (int idx = t; idx < 2*NK3*16; idx += 256) {
            int cw = idx & 15; int sk = idx >> 4; int k = sk % NK3; int s = sk / NK3;
            sw[s][k][cw] = w3[((s*Ss + e)*NK3 + k)*Cc + c0 + cw];
        }
        __syncthreads();
        int m = t & 63;
        int cq = t >> 6;
        bool valid = (m0 + m) < NM3;
        int cl = cq*4;
        float s00=0,s01=0,s02=0,s03=0, s10=0,s11=0,s12=0,s13=0;
        float s20=0,s21=0,s22=0,s23=0, s30=0,s31=0,s32=0,s33=0;
        #pragma unroll
        for (int k = 0; k < NK3; k++) {
            float u0 = su[0][k][m], u1 = su[1][k][m];
            float u2 = su[2][k][m], u3 = su[3][k][m];
            float4 wa = *reinterpret_cast<float4*>(&sw[0][k][cl]);   // warp-uniform
            float4 wb = *reinterpret_cast<float4*>(&sw[1][k][cl]);
            s00 += u0*wa.x; s01 += u1*wb.x; s02 += u2*wb.x; s03 += u3*wb.x;
            s10 += u0*wa.y; s11 += u1*wb.y; s12 += u2*wb.y; s13 += u3*wb.y;
            s20 += u0*wa.z; s21 += u1*wb.z; s22 += u2*wb.z; s23 += u3*wb.z;
            s30 += u0*wa.w; s31 += u1*wb.w; s32 += u2*wb.w; s33 += u3*wb.w;
        }
        if (valid) {
            int mm = m0 + m;
            g_uw3s[(e*Cc + c0 + cl + 0)*NM3 + mm] = make_float4(s00,s01,s02,s03);
            g_uw3s[(e*Cc + c0 + cl + 1)*NM3 + mm] = make_float4(s10,s11,s12,s13);
            g_uw3s[(e*Cc + c0 + cl + 2)*NM3 + mm] = make_float4(s20,s21,s22,s23);
            g_uw3s[(e*Cc + c0 + cl + 3)*NM3 + mm] = make_float4(s30,s31,s32,s33);
        }
    } else if (blk < F3_BLKS + F2_BLKS) {
        int tid = (blk - F3_BLKS)*256 + t;
        int m = tid % NM2; int ec = tid / NM2;
        int c = ec % Cc;   int e  = ec / Cc;
        const float* w0  = w2 + ((0*Ss + e)*NK2)*Cc + c;
        const float* w1v = w2 + ((1*Ss + e)*NK2)*Cc + c;
        float s0=0.f, s1=0.f, s2=0.f, s3=0.f;
        #pragma unroll
        for (int k = 0; k < NK2; k++) {
            float a = __ldg(w0 + k*Cc), b = __ldg(w1v + k*Cc);   // warp-uniform
            s0 += g_u2s[(0*NK2 + k)*NM2 + m]*a;
            s1 += g_u2s[(1*NK2 + k)*NM2 + m]*b;
            s2 += g_u2s[(2*NK2 + k)*NM2 + m]*b;
            s3 += g_u2s[(3*NK2 + k)*NM2 + m]*b;
        }
        g_uw2s[tid] = make_float4(s0,s1,s2,s3);
    } else {
        int tid = (blk - F3_BLKS - F2_BLKS)*256 + t;
        int i = tid % Dd; int ec = tid / Dd;
        int c = ec % Cc;  int e  = ec / Cc;
        float s[OT];
        #pragma unroll
        for (int o = 0; o < OT; o++) {
            int set = (o == 0) ? 0 : 1;
            float acc = 0.f;
            #pragma unroll
            for (int k = 0; k < NK1; k++) {
                float uv = (o == 0) ? u1_0[i*NK1 + k]
                                    : u1_1[(((o-1)*Dd) + i)*NK1 + k];
                acc += uv * w1[((set*Ss + e)*NK1 + k)*Cc + c];
            }
            s[o] = acc;
        }
        g_uw1s[tid] = make_float4(s[0], s[1], s[2], s[3]);
    }
}

// ---------------- main symmetric-contraction kernel (R7-exact) ----------------
#define FMA2(acc, a, b) asm("fma.rn.f32x2 %0, %1, %2, %0;" : "+l"(acc) : "l"(a), "l"(b))
#define MUL2(d, a, b)   asm("mul.rn.f32x2 %0, %1, %2;" : "=l"(d) : "l"(a), "l"(b))

__global__ void __launch_bounds__(128) k_main(const float* __restrict__ nf) {
    __shared__ ulonglong2 su3[NM3];     // 13056 B
    __shared__ ulonglong2 su2[NM2];     //  2176 B
    __shared__ ulonglong2 su1[Dd];      //   256 B
    int c = blockIdx.x, e = blockIdx.y, half = blockIdx.z;
    int t = threadIdx.x;
    int ec = e*Cc + c;
    const ulonglong2* G3 = reinterpret_cast<const ulonglong2*>(g_uw3s) + ec*NM3;
    const ulonglong2* G2 = reinterpret_cast<const ulonglong2*>(g_uw2s) + ec*NM2;
    const ulonglong2* G1 = reinterpret_cast<const ulonglong2*>(g_uw1s) + ec*Dd;
    for (int idx = t; idx < NM3; idx += 128) su3[idx] = G3[idx];
    for (int idx = t; idx < NM2; idx += 128) su2[idx] = G2[idx];
    if (t < Dd) su1[t] = G1[t];
    __syncthreads();
    int n = g_count[e];
    int off = 0;
    for (int q = 0; q < Ss; q++) if (q < e) off += g_count[q];
    for (int base = half*128; base < n; base += 256) {
        int li = base + t;
        if (li >= n) continue;            // no barriers below: safe divergence
        int p = off + li;
        int b = g_pb[p];
        const float4* src = reinterpret_cast<const float4*>(nf + (b*Cc + c)*Dd);
        float4 v0 = src[0], v1 = src[1], v2 = src[2], v3 = src[3];
        float x[16] = {v0.x,v0.y,v0.z,v0.w, v1.x,v1.y,v1.z,v1.w,
                       v2.x,v2.y,v2.z,v2.w, v3.x,v3.y,v3.z,v3.w};
        u64 xd[16];                        // {x_i, x_i} packed
        #pragma unroll
        for (int i = 0; i < 16; i++) {
            unsigned xi = __float_as_uint(x[i]);
            asm("mov.b64 %0, {%1, %1};" : "=l"(xd[i]) : "r"(xi));
        }
        u64 acc01 = 0ull, acc23 = 0ull;    // {a0,a1}, {a2,a3}
        int m3 = 0, m2 = 0;
        #pragma unroll
        for (int j = 0; j < 16; j++) {     // unrolled: (16-j) known per copy
            u64 xj = xd[j];
            ulonglong2 u1r = su1[j];
            FMA2(acc01, u1r.x, xj);
            FMA2(acc23, u1r.y, xj);
            const int w = 16 - j;
            #pragma unroll 1
            for (int i = 0; i <= j; i++) { // rolled: keeps code small
                u64 xx; MUL2(xx, xd[i], xj);
                ulonglong2 u2r = su2[m2 + i];
                u64 d01 = u2r.x, d23 = u2r.y;    // dot = u2 + sum_l u3*x_l
                const ulonglong2* s3 = &su3[m3 + i*w];
                #pragma unroll
                for (int l = j; l < 16; l++) {
                    ulonglong2 u = s3[l - j];     // LDS.128 broadcast
                    FMA2(d01, u.x, xd[l]);
                    FMA2(d23, u.y, xd[l]);
                }
                FMA2(acc01, xx, d01);            // acc += xx * dot
                FMA2(acc23, xx, d23);
            }
            m2 += j + 1;
            m3 += (j + 1) * w;
        }
        unsigned r0, r1, r2, r3;
        asm("mov.b64 {%0,%1}, %2;" : "=r"(r0), "=r"(r1) : "l"(acc01));
        asm("mov.b64 {%0,%1}, %2;" : "=r"(r2), "=r"(r3) : "l"(acc23));
        g_Y[(0*Cc + c)*Bn + p] = __uint_as_float(r0);   // coalesced: p = off+base+t
        g_Y[(1*Cc + c)*Bn + p] = __uint_as_float(r1);
        g_Y[(2*Cc + c)*Bn + p] = __uint_as_float(r2);
        g_Y[(3*Cc + c)*Bn + p] = __uint_as_float(r3);
    }
}

// ---------------- final equivariant linear (R7-exact: one wave, 512 thr) ----------------
#define LIN_SMEM (Cc*Cc*4 + Cc*32*4)   // Ws 64KB + Ys 16KB = 81920 B
__global__ void __launch_bounds__(512) k_linear(const float* __restrict__ wlin,
                                                float* __restrict__ out) {
    extern __shared__ float sm[];
    float* Ws = sm;              // [128][128]
    float* Ys = sm + Cc*Cc;      // [128][32]
    int o  = blockIdx.y;
    int p0 = blockIdx.x * 32;
    int set = (o == 0) ? 0 : 1;
    int t  = threadIdx.x;
    const float4* wsrc = reinterpret_cast<const float4*>(wlin + set*Cc*Cc);
    float4* wdst = reinterpret_cast<float4*>(Ws);
    #pragma unroll
    for (int idx = t; idx < Cc*Cc/4; idx += 512) wdst[idx] = wsrc[idx];
    #pragma unroll
    for (int idx = t; idx < Cc*32; idx += 512) {
        int cc = idx >> 5, pp = idx & 31;
        Ys[cc*32 + pp] = g_Y[(o*Cc + cc)*Bn + p0 + pp];
    }
    __syncthreads();
    int tp = t & 15;          // 16 row-slots x 2 rows = 32
    int tn = t >> 4;          // 32 col-slots x 4 cols = 128
    float a0x=0,a0y=0,a0z=0,a0w=0, a1x=0,a1y=0,a1z=0,a1w=0;
    #pragma unroll 16
    for (int cc = 0; cc < Cc; cc++) {
        float2 y = *reinterpret_cast<const float2*>(&Ys[cc*32 + tp*2]);   // broadcast-dedup
        float4 w = *reinterpret_cast<const float4*>(&Ws[cc*Cc + tn*4]);   // broadcast-dedup
        a0x += y.x*w.x; a0y += y.x*w.y; a0z += y.x*w.z; a0w += y.x*w.w;
        a1x += y.y*w.x; a1y += y.y*w.y; a1z += y.y*w.z; a1w += y.y*w.w;
    }
    const float scale = 0.08838834764831845f;    // 1/sqrt(128)
    float4 r0 = make_float4(a0x*scale, a0y*scale, a0z*scale, a0w*scale);
    float4 r1 = make_float4(a1x*scale, a1y*scale, a1z*scale, a1w*scale);
    int p_a = p0 + tp*2;
    int b0 = g_pb[p_a + 0], b1 = g_pb[p_a + 1];
    if (o == 0) {
        *reinterpret_cast<float4*>(&out[b0*512 + tn*4]) = r0;
        *reinterpret_cast<float4*>(&out[b1*512 + tn*4]) = r1;
    } else {
        int op = o - 1;
        float* o0 = &out[b0*512 + 128 + op];
        float* o1 = &out[b1*512 + 128 + op];
        o0[(tn*4+0)*3] = r0.x; o0[(tn*4+1)*3] = r0.y; o0[(tn*4+2)*3] = r0.z; o0[(tn*4+3)*3] = r0.w;
        o1[(tn*4+0)*3] = r1.x; o1[(tn*4+1)*3] = r1.y; o1[(tn*4+2)*3] = r1.z; o1[(tn*4+3)*3] = r1.w;
    }
}

// ---------------- launch (4 launches, R7 structure) ----------------
extern "C" void kernel_launch(void* const* d_in, const int* in_sizes, int n_in,
                              void* d_out, int out_size) {
    const float* nf   = (const float*)d_in[0];
    const float* u3_0 = (const float*)d_in[1];
    const float* u3_1 = (const float*)d_in[2];
    const float* u2_0 = (const float*)d_in[3];
    const float* u2_1 = (const float*)d_in[4];
    const float* u1_0 = (const float*)d_in[5];
    const float* u1_1 = (const float*)d_in[6];
    const float* w3   = (const float*)d_in[7];
    const float* w2   = (const float*)d_in[8];
    const float* w1   = (const float*)d_in[9];
    const float* wl   = (const float*)d_in[10];
    const int*   sp   = (const int*)d_in[11];
    float* out = (float*)d_out;

    cudaFuncSetAttribute(k_linear, cudaFuncAttributeMaxDynamicSharedMemorySize, LIN_SMEM);

    k_prep<<<1 + SYM3_BLKS + 4, 256>>>(sp, u3_0, u3_1, u2_0, u2_1);
    k_fold<<<F3_BLKS + F2_BLKS + F1_BLKS, 256>>>(w3, w2, u1_0, u1_1, w1);
    k_main<<<dim3(Cc, Ss, 2), 128>>>(nf);
    k_linear<<<dim3(Bn/32, 4), 512, LIN_SMEM>>>(wl, out);
}

// round 16
// speedup vs baseline: 1.0571x; 1.0004x over previous
#include <cuda_runtime.h>

#define Bn 1024
#define Cc 128
#define Dd 16
#define Ss 4
#define NK3 23
#define NK2 5
#define NK1 2
#define NM3 816   // # monomials, ordered by (j, i, l): m = off3[j] + i*(16-j) + (l-j)
#define NM2 136   // # pairs, ordered by (j, i): m = j(j+1)/2 + i
#define OT 4      // total output irrep components: 1 (0e) + 3 (1o)

typedef unsigned long long u64;

// ---------------- scratch (device globals; no allocation allowed) ----------------
__device__ float  g_u3s[OT*NM3*NK3 + 512]; // symmetrized u3, layout [o][m][k] (+pad)
__device__ float  g_u2s[OT*NK2*NM2];       // symmetrized u2, layout [o][k][m]
__device__ float4 g_uw3s[Ss*Cc*NM3];       // per-(species,channel) weighted basis, float4 over o
__device__ float4 g_uw2s[Ss*Cc*NM2];
__device__ float4 g_uw1s[Ss*Cc*Dd];
__device__ float  g_Y[OT*Cc*Bn];           // y[o][c][p]  (p = species-compact position)
__device__ int    g_count[Ss];
__device__ int    g_list[Ss*Bn];
__device__ int    g_pb[Bn];                // compact position -> node index

// ---------------- prep: species sort/compact + symmetrize u3/u2 (R7-exact) ----------------
__device__ __forceinline__ float u3at(const float* __restrict__ u3_0,
                                      const float* __restrict__ u3_1,
                                      int o, int a, int b, int c, int k) {
    if (o == 0) return u3_0[((a*Dd + b)*Dd + c)*NK3 + k];
    return u3_1[((((o-1)*Dd + a)*Dd + b)*Dd + c)*NK3 + k];
}

#define SYM3_BLKS 294
__global__ void k_prep(const int* __restrict__ sp,
                       const float* __restrict__ u3_0, const float* __restrict__ u3_1,
                       const float* __restrict__ u2_0, const float* __restrict__ u2_1) {
    int blk = blockIdx.x;
    int t = threadIdx.x;                 // 256 threads
    if (blk == 0) {
        // species counting-sort + compaction (single block so ordering is safe)
        if (t < Ss) g_count[t] = 0;
        __syncthreads();
        for (int b = t; b < Bn; b += 256) {
            int e = sp[b];
            int pos = atomicAdd(&g_count[e], 1);
            g_list[e*Bn + pos] = b;
        }
        __syncthreads();
        int off = 0;
        for (int e = 0; e < Ss; e++) {
            int n = g_count[e];
            for (int i = t; i < n; i += 256) g_pb[off + i] = g_list[e*Bn + i];
            off += n;
        }
    } else if (blk <= SYM3_BLKS) {
        // symmetrize u3 -> g_u3s[o][m][k], thread per (o,m,k); equality-case perms
        int tid = (blk-1)*256 + t;
        if (tid >= OT*NM3*NK3) return;
        int k  = tid % NK3;
        int om = tid / NK3;
        int m  = om % NM3;
        int o  = om / NM3;
        const int off3[17] = {0,16,46,88,140,200,266,336,408,480,550,616,676,728,770,800,816};
        int j = 0;
        #pragma unroll
        for (int q = 1; q < 16; q++) if (m >= off3[q]) j = q;
        int r = m - off3[j];
        int w = 16 - j;
        int i = r / w;          // i <= j
        int l = j + r % w;      // l >= j
        float s = u3at(u3_0, u3_1, o, i, j, l, k);
        if (i < j && j < l) {
            s += u3at(u3_0, u3_1, o, i, l, j, k) + u3at(u3_0, u3_1, o, j, i, l, k)
               + u3at(u3_0, u3_1, o, j, l, i, k) + u3at(u3_0, u3_1, o, l, i, j, k)
               + u3at(u3_0, u3_1, o, l, j, i, k);
        } else if (i == j && j < l) {
            s += u3at(u3_0, u3_1, o, i, l, i, k) + u3at(u3_0, u3_1, o, l, i, i, k);
        } else if (i < j && j == l) {
            s += u3at(u3_0, u3_1, o, j, i, j, k) + u3at(u3_0, u3_1, o, j, j, i, k);
        }
        g_u3s[(o*NM3 + m)*NK3 + k] = s;    // coalesced over k
    } else {
        // symmetrize u2 -> g_u2s[o][k][m], pair order (j,i)
        int tid = (blk-SYM3_BLKS-1)*256 + t;   // 0..1023 = 4 * 256
        if (tid >= OT*256) return;
        int o = tid >> 8;
        int r = tid & 255;
        int i = (r >> 4) & 15, j = r & 15;
        if (i > j) return;
        int m = j*(j+1)/2 + i;
        for (int k = 0; k < NK2; k++) {
            float s;
            if (o == 0) {
                s = u2_0[(i*Dd + j)*NK2 + k];
                if (i != j) s += u2_0[(j*Dd + i)*NK2 + k];
            } else {
                s = u2_1[(((o-1)*Dd + i)*Dd + j)*NK2 + k];
                if (i != j) s += u2_1[(((o-1)*Dd + j)*Dd + i)*NK2 + k];
            }
            g_u2s[(o*NK2 + k)*NM2 + m] = s;
        }
    }
}

// ---------------- fold: species weights into bases ----------------
// fold3: 416 CTAs = 4 species x 13 m-tiles(64) x 8 c-blocks(16)  [R14: was 208 x 32-col]
#define F3_BLKS 416
#define F2_BLKS (Ss*Cc*NM2/256)   // 272
#define F1_BLKS (Ss*Cc*Dd/256)    // 32

__global__ void __launch_bounds__(256) k_fold(
        const float* __restrict__ w3, const float* __restrict__ w2,
        const float* __restrict__ u1_0, const float* __restrict__ u1_1,
        const float* __restrict__ w1) {
    int blk = blockIdx.x;
    int t = threadIdx.x;
    if (blk < F3_BLKS) {
        __shared__ float su[OT][NK3][64];   // 23.5 KB
        __shared__ float sw[2][NK3][16];    //  2.9 KB
        int e  = blk / 104;
        int r  = blk % 104;
        int m0 = (r >> 3) * 64;
        int c0 = (r & 7) * 16;
        for (int idx = t; idx < OT*NK3*64; idx += 256) {
            int k = idx % NK3; int mo = idx / NK3; int m = mo & 63; int o = mo >> 6;
            su[o][k][m] = g_u3s[(o*NM3 + m0 + m)*NK3 + k];   // may over-read into pad
        }
        for (int idx = t; idx < 2*NK3*16; idx += 256) {
            int cw = idx & 15; int sk = idx >> 4; int k = sk % NK3; int s = sk / NK3;
            sw[s][k][cw] = w3[((s*Ss + e)*NK3 + k)*Cc + c0 + cw];
        }
        __syncthreads();
        int m = t & 63;
        int cq = t >> 6;
        bool valid = (m0 + m) < NM3;
        int cl = cq*4;
        float s00=0,s01=0,s02=0,s03=0, s10=0,s11=0,s12=0,s13=0;
        float s20=0,s21=0,s22=0,s23=0, s30=0,s31=0,s32=0,s33=0;
        #pragma unroll
        for (int k = 0; k < NK3; k++) {
            float u0 = su[0][k][m], u1 = su[1][k][m];
            float u2 = su[2][k][m], u3 = su[3][k][m];
            float4 wa = *reinterpret_cast<float4*>(&sw[0][k][cl]);   // warp-uniform
            float4 wb = *reinterpret_cast<float4*>(&sw[1][k][cl]);
            s00 += u0*wa.x; s01 += u1*wb.x; s02 += u2*wb.x; s03 += u3*wb.x;
            s10 += u0*wa.y; s11 += u1*wb.y; s12 += u2*wb.y; s13 += u3*wb.y;
            s20 += u0*wa.z; s21 += u1*wb.z; s22 += u2*wb.z; s23 += u3*wb.z;
            s30 += u0*wa.w; s31 += u1*wb.w; s32 += u2*wb.w; s33 += u3*wb.w;
        }
        if (valid) {
            int mm = m0 + m;
            g_uw3s[(e*Cc + c0 + cl + 0)*NM3 + mm] = make_float4(s00,s01,s02,s03);
            g_uw3s[(e*Cc + c0 + cl + 1)*NM3 + mm] = make_float4(s10,s11,s12,s13);
            g_uw3s[(e*Cc + c0 + cl + 2)*NM3 + mm] = make_float4(s20,s21,s22,s23);
            g_uw3s[(e*Cc + c0 + cl + 3)*NM3 + mm] = make_float4(s30,s31,s32,s33);
        }
    } else if (blk < F3_BLKS + F2_BLKS) {
        int tid = (blk - F3_BLKS)*256 + t;
        int m = tid % NM2; int ec = tid / NM2;
        int c = ec % Cc;   int e  = ec / Cc;
        const float* w0  = w2 + ((0*Ss + e)*NK2)*Cc + c;
        const float* w1v = w2 + ((1*Ss + e)*NK2)*Cc + c;
        float s0=0.f, s1=0.f, s2=0.f, s3=0.f;
        #pragma unroll
        for (int k = 0; k < NK2; k++) {
            float a = __ldg(w0 + k*Cc), b = __ldg(w1v + k*Cc);   // warp-uniform
            s0 += g_u2s[(0*NK2 + k)*NM2 + m]*a;
            s1 += g_u2s[(1*NK2 + k)*NM2 + m]*b;
            s2 += g_u2s[(2*NK2 + k)*NM2 + m]*b;
            s3 += g_u2s[(3*NK2 + k)*NM2 + m]*b;
        }
        g_uw2s[tid] = make_float4(s0,s1,s2,s3);
    } else {
        int tid = (blk - F3_BLKS - F2_BLKS)*256 + t;
        int i = tid % Dd; int ec = tid / Dd;
        int c = ec % Cc;  int e  = ec / Cc;
        float s[OT];
        #pragma unroll
        for (int o = 0; o < OT; o++) {
            int set = (o == 0) ? 0 : 1;
            float acc = 0.f;
            #pragma unroll
            for (int k = 0; k < NK1; k++) {
                float uv = (o == 0) ? u1_0[i*NK1 + k]
                                    : u1_1[(((o-1)*Dd) + i)*NK1 + k];
                acc += uv * w1[((set*Ss + e)*NK1 + k)*Cc + c];
            }
            s[o] = acc;
        }
        g_uw1s[tid] = make_float4(s[0], s[1], s[2], s[3]);
    }
}

// ---------------- main symmetric-contraction kernel (R7-exact) ----------------
#define FMA2(acc, a, b) asm("fma.rn.f32x2 %0, %1, %2, %0;" : "+l"(acc) : "l"(a), "l"(b))
#define MUL2(d, a, b)   asm("mul.rn.f32x2 %0, %1, %2;" : "=l"(d) : "l"(a), "l"(b))

__global__ void __launch_bounds__(128) k_main(const float* __restrict__ nf) {
    __shared__ ulonglong2 su3[NM3];     // 13056 B
    __shared__ ulonglong2 su2[NM2];     //  2176 B
    __shared__ ulonglong2 su1[Dd];      //   256 B
    int c = blockIdx.x, e = blockIdx.y, half = blockIdx.z;
    int t = threadIdx.x;
    int ec = e*Cc + c;
    const ulonglong2* G3 = reinterpret_cast<const ulonglong2*>(g_uw3s) + ec*NM3;
    const ulonglong2* G2 = reinterpret_cast<const ulonglong2*>(g_uw2s) + ec*NM2;
    const ulonglong2* G1 = reinterpret_cast<const ulonglong2*>(g_uw1s) + ec*Dd;
    for (int idx = t; idx < NM3; idx += 128) su3[idx] = G3[idx];
    for (int idx = t; idx < NM2; idx += 128) su2[idx] = G2[idx];
    if (t < Dd) su1[t] = G1[t];
    __syncthreads();
    int n = g_count[e];
    int off = 0;
    for (int q = 0; q < Ss; q++) if (q < e) off += g_count[q];
    for (int base = half*128; base < n; base += 256) {
        int li = base + t;
        if (li >= n) continue;            // no barriers below: safe divergence
        int p = off + li;
        int b = g_pb[p];
        const float4* src = reinterpret_cast<const float4*>(nf + (b*Cc + c)*Dd);
        float4 v0 = src[0], v1 = src[1], v2 = src[2], v3 = src[3];
        float x[16] = {v0.x,v0.y,v0.z,v0.w, v1.x,v1.y,v1.z,v1.w,
                       v2.x,v2.y,v2.z,v2.w, v3.x,v3.y,v3.z,v3.w};
        u64 xd[16];                        // {x_i, x_i} packed
        #pragma unroll
        for (int i = 0; i < 16; i++) {
            unsigned xi = __float_as_uint(x[i]);
            asm("mov.b64 %0, {%1, %1};" : "=l"(xd[i]) : "r"(xi));
        }
        u64 acc01 = 0ull, acc23 = 0ull;    // {a0,a1}, {a2,a3}
        int m3 = 0, m2 = 0;
        #pragma unroll
        for (int j = 0; j < 16; j++) {     // unrolled: (16-j) known per copy
            u64 xj = xd[j];
            ulonglong2 u1r = su1[j];
            FMA2(acc01, u1r.x, xj);
            FMA2(acc23, u1r.y, xj);
            const int w = 16 - j;
            #pragma unroll 1
            for (int i = 0; i <= j; i++) { // rolled: keeps code small
                u64 xx; MUL2(xx, xd[i], xj);
                ulonglong2 u2r = su2[m2 + i];
                u64 d01 = u2r.x, d23 = u2r.y;    // dot = u2 + sum_l u3*x_l
                const ulonglong2* s3 = &su3[m3 + i*w];
                #pragma unroll
                for (int l = j; l < 16; l++) {
                    ulonglong2 u = s3[l - j];     // LDS.128 broadcast
                    FMA2(d01, u.x, xd[l]);
                    FMA2(d23, u.y, xd[l]);
                }
                FMA2(acc01, xx, d01);            // acc += xx * dot
                FMA2(acc23, xx, d23);
            }
            m2 += j + 1;
            m3 += (j + 1) * w;
        }
        unsigned r0, r1, r2, r3;
        asm("mov.b64 {%0,%1}, %2;" : "=r"(r0), "=r"(r1) : "l"(acc01));
        asm("mov.b64 {%0,%1}, %2;" : "=r"(r2), "=r"(r3) : "l"(acc23));
        g_Y[(0*Cc + c)*Bn + p] = __uint_as_float(r0);   // coalesced: p = off+base+t
        g_Y[(1*Cc + c)*Bn + p] = __uint_as_float(r1);
        g_Y[(2*Cc + c)*Bn + p] = __uint_as_float(r2);
        g_Y[(3*Cc + c)*Bn + p] = __uint_as_float(r3);
    }
}

// ---------------- final equivariant linear (R7-exact: one wave, 512 thr) ----------------
#define LIN_SMEM (Cc*Cc*4 + Cc*32*4)   // Ws 64KB + Ys 16KB = 81920 B
__global__ void __launch_bounds__(512) k_linear(const float* __restrict__ wlin,
                                                float* __restrict__ out) {
    extern __shared__ float sm[];
    float* Ws = sm;              // [128][128]
    float* Ys = sm + Cc*Cc;      // [128][32]
    int o  = blockIdx.y;
    int p0 = blockIdx.x * 32;
    int set = (o == 0) ? 0 : 1;
    int t  = threadIdx.x;
    const float4* wsrc = reinterpret_cast<const float4*>(wlin + set*Cc*Cc);
    float4* wdst = reinterpret_cast<float4*>(Ws);
    #pragma unroll
    for (int idx = t; idx < Cc*Cc/4; idx += 512) wdst[idx] = wsrc[idx];
    #pragma unroll
    for (int idx = t; idx < Cc*32; idx += 512) {
        int cc = idx >> 5, pp = idx & 31;
        Ys[cc*32 + pp] = g_Y[(o*Cc + cc)*Bn + p0 + pp];
    }
    __syncthreads();
    int tp = t & 15;          // 16 row-slots x 2 rows = 32
    int tn = t >> 4;          // 32 col-slots x 4 cols = 128
    float a0x=0,a0y=0,a0z=0,a0w=0, a1x=0,a1y=0,a1z=0,a1w=0;
    #pragma unroll 16
    for (int cc = 0; cc < Cc; cc++) {
        float2 y = *reinterpret_cast<const float2*>(&Ys[cc*32 + tp*2]);   // broadcast-dedup
        float4 w = *reinterpret_cast<const float4*>(&Ws[cc*Cc + tn*4]);   // broadcast-dedup
        a0x += y.x*w.x; a0y += y.x*w.y; a0z += y.x*w.z; a0w += y.x*w.w;
        a1x += y.y*w.x; a1y += y.y*w.y; a1z += y.y*w.z; a1w += y.y*w.w;
    }
    const float scale = 0.08838834764831845f;    // 1/sqrt(128)
    float4 r0 = make_float4(a0x*scale, a0y*scale, a0z*scale, a0w*scale);
    float4 r1 = make_float4(a1x*scale, a1y*scale, a1z*scale, a1w*scale);
    int p_a = p0 + tp*2;
    int b0 = g_pb[p_a + 0], b1 = g_pb[p_a + 1];
    if (o == 0) {
        *reinterpret_cast<float4*>(&out[b0*512 + tn*4]) = r0;
        *reinterpret_cast<float4*>(&out[b1*512 + tn*4]) = r1;
    } else {
        int op = o - 1;
        float* o0 = &out[b0*512 + 128 + op];
        float* o1 = &out[b1*512 + 128 + op];
        o0[(tn*4+0)*3] = r0.x; o0[(tn*4+1)*3] = r0.y; o0[(tn*4+2)*3] = r0.z; o0[(tn*4+3)*3] = r0.w;
        o1[(tn*4+0)*3] = r1.x; o1[(tn*4+1)*3] = r1.y; o1[(tn*4+2)*3] = r1.z; o1[(tn*4+3)*3] = r1.w;
    }
}

// ---------------- launch (4 launches, R7 structure) ----------------
extern "C" void kernel_launch(void* const* d_in, const int* in_sizes, int n_in,
                              void* d_out, int out_size) {
    const float* nf   = (const float*)d_in[0];
    const float* u3_0 = (const float*)d_in[1];
    const float* u3_1 = (const float*)d_in[2];
    const float* u2_0 = (const float*)d_in[3];
    const float* u2_1 = (const float*)d_in[4];
    const float* u1_0 = (const float*)d_in[5];
    const float* u1_1 = (const float*)d_in[6];
    const float* w3   = (const float*)d_in[7];
    const float* w2   = (const float*)d_in[8];
    const float* w1   = (const float*)d_in[9];
    const float* wl   = (const float*)d_in[10];
    const int*   sp   = (const int*)d_in[11];
    float* out = (float*)d_out;

    cudaFuncSetAttribute(k_linear, cudaFuncAttributeMaxDynamicSharedMemorySize, LIN_SMEM);

    k_prep<<<1 + SYM3_BLKS + 4, 256>>>(sp, u3_0, u3_1, u2_0, u2_1);
    k_fold<<<F3_BLKS + F2_BLKS + F1_BLKS, 256>>>(w3, w2, u1_0, u1_1, w1);
    k_main<<<dim3(Cc, Ss, 2), 128>>>(nf);
    k_linear<<<dim3(Bn/32, 4), 512, LIN_SMEM>>>(wl, out);
}

// round 17
// speedup vs baseline: 1.0862x; 1.0276x over previous
#include <cuda_runtime.h>

#define Bn 1024
#define Cc 128
#define Dd 16
#define Ss 4
#define NK3 23
#define NK2 5
#define NK1 2
#define NM3 816   // # monomials, ordered by (j, i, l): m = off3[j] + i*(16-j) + (l-j)
#define NM2 136   // # pairs, ordered by (j, i): m = j(j+1)/2 + i
#define OT 4      // total output irrep components: 1 (0e) + 3 (1o)

typedef unsigned long long u64;

// ---------------- scratch (device globals; no allocation allowed) ----------------
__device__ float  g_u3s[OT*NM3*NK3 + 512]; // symmetrized u3, layout [o][m][k] (+pad)
__device__ float  g_u2s[OT*NK2*NM2];       // symmetrized u2, layout [o][k][m]
__device__ float4 g_uw3s[Ss*Cc*NM3];       // per-(species,channel) weighted basis, float4 over o
__device__ float4 g_uw2s[Ss*Cc*NM2];
__device__ float4 g_uw1s[Ss*Cc*Dd];
__device__ float  g_Y[OT*Cc*Bn];           // y[o][c][p]  (p = species-compact position)
__device__ int    g_count[Ss];
__device__ int    g_list[Ss*Bn];
__device__ int    g_pb[Bn];                // compact position -> node index

// ---------------- prep: species sort/compact + symmetrize u3/u2 ----------------
__device__ __forceinline__ float u3at(const float* __restrict__ u3_0,
                                      const float* __restrict__ u3_1,
                                      int o, int a, int b, int c, int k) {
    if (o == 0) return u3_0[((a*Dd + b)*Dd + c)*NK3 + k];
    return u3_1[((((o-1)*Dd + a)*Dd + b)*Dd + c)*NK3 + k];
}

#define SYM3_BLKS 294
__global__ void k_prep(const int* __restrict__ sp,
                       const float* __restrict__ u3_0, const float* __restrict__ u3_1,
                       const float* __restrict__ u2_0, const float* __restrict__ u2_1) {
    int blk = blockIdx.x;
    int t = threadIdx.x;                 // 256 threads
    if (blk == 0) {
        // species counting-sort + compaction (single block so ordering is safe)
        if (t < Ss) g_count[t] = 0;
        __syncthreads();
        for (int b = t; b < Bn; b += 256) {
            int e = sp[b];
            int pos = atomicAdd(&g_count[e], 1);
            g_list[e*Bn + pos] = b;
        }
        __syncthreads();
        int off = 0;
        for (int e = 0; e < Ss; e++) {
            int n = g_count[e];
            for (int i = t; i < n; i += 256) g_pb[off + i] = g_list[e*Bn + i];
            off += n;
        }
    } else if (blk <= SYM3_BLKS) {
        // symmetrize u3 -> g_u3s[o][m][k], thread per (o,m,k); equality-case perms
        int tid = (blk-1)*256 + t;
        if (tid >= OT*NM3*NK3) return;
        int k  = tid % NK3;
        int om = tid / NK3;
        int m  = om % NM3;
        int o  = om / NM3;
        const int off3[17] = {0,16,46,88,140,200,266,336,408,480,550,616,676,728,770,800,816};
        int j = 0;
        #pragma unroll
        for (int q = 1; q < 16; q++) if (m >= off3[q]) j = q;
        int r = m - off3[j];
        int w = 16 - j;
        int i = r / w;          // i <= j
        int l = j + r % w;      // l >= j
        float s = u3at(u3_0, u3_1, o, i, j, l, k);
        if (i < j && j < l) {
            s += u3at(u3_0, u3_1, o, i, l, j, k) + u3at(u3_0, u3_1, o, j, i, l, k)
               + u3at(u3_0, u3_1, o, j, l, i, k) + u3at(u3_0, u3_1, o, l, i, j, k)
               + u3at(u3_0, u3_1, o, l, j, i, k);
        } else if (i == j && j < l) {
            s += u3at(u3_0, u3_1, o, i, l, i, k) + u3at(u3_0, u3_1, o, l, i, i, k);
        } else if (i < j && j == l) {
            s += u3at(u3_0, u3_1, o, j, i, j, k) + u3at(u3_0, u3_1, o, j, j, i, k);
        }
        g_u3s[(o*NM3 + m)*NK3 + k] = s;    // coalesced over k
    } else {
        // symmetrize u2 -> g_u2s[o][k][m], pair order (j,i)
        int tid = (blk-SYM3_BLKS-1)*256 + t;   // 0..1023 = 4 * 256
        if (tid >= OT*256) return;
        int o = tid >> 8;
        int r = tid & 255;
        int i = (r >> 4) & 15, j = r & 15;
        if (i > j) return;
        int m = j*(j+1)/2 + i;
        for (int k = 0; k < NK2; k++) {
            float s;
            if (o == 0) {
                s = u2_0[(i*Dd + j)*NK2 + k];
                if (i != j) s += u2_0[(j*Dd + i)*NK2 + k];
            } else {
                s = u2_1[(((o-1)*Dd + i)*Dd + j)*NK2 + k];
                if (i != j) s += u2_1[(((o-1)*Dd + j)*Dd + i)*NK2 + k];
            }
            g_u2s[(o*NK2 + k)*NM2 + m] = s;
        }
    }
}

// ---------------- fold: species weights into bases (R7-exact, 208 CTAs) ----------------
#define F3_BLKS 208
#define F2_BLKS (Ss*Cc*NM2/256)   // 272
#define F1_BLKS (Ss*Cc*Dd/256)    // 32

__global__ void __launch_bounds__(256) k_fold(
        const float* __restrict__ w3, const float* __restrict__ w2,
        const float* __restrict__ u1_0, const float* __restrict__ u1_1,
        const float* __restrict__ w1) {
    int blk = blockIdx.x;
    int t = threadIdx.x;
    if (blk < F3_BLKS) {
        __shared__ float su[OT][NK3][64];   // 23.5 KB
        __shared__ float sw[2][NK3][32];    //  5.9 KB
        int e  = blk / 52;
        int r  = blk % 52;
        int m0 = (r >> 2) * 64;
        int c0 = (r & 3) * 32;
        for (int idx = t; idx < OT*NK3*64; idx += 256) {
            int k = idx % NK3; int mo = idx / NK3; int m = mo & 63; int o = mo >> 6;
            su[o][k][m] = g_u3s[(o*NM3 + m0 + m)*NK3 + k];   // may over-read into pad
        }
        for (int idx = t; idx < 2*NK3*32; idx += 256) {
            int cw = idx & 31; int sk = idx >> 5; int k = sk % NK3; int s = sk / NK3;
            sw[s][k][cw] = w3[((s*Ss + e)*NK3 + k)*Cc + c0 + cw];
        }
        __syncthreads();
        int m = t & 63;
        int cq = t >> 6;
        bool valid = (m0 + m) < NM3;
        #pragma unroll
        for (int ci = 0; ci < 2; ci++) {
            int cl = cq*8 + ci*4;
            float s00=0,s01=0,s02=0,s03=0, s10=0,s11=0,s12=0,s13=0;
            float s20=0,s21=0,s22=0,s23=0, s30=0,s31=0,s32=0,s33=0;
            #pragma unroll
            for (int k = 0; k < NK3; k++) {
                float u0 = su[0][k][m], u1 = su[1][k][m];
                float u2 = su[2][k][m], u3 = su[3][k][m];
                float4 wa = *reinterpret_cast<float4*>(&sw[0][k][cl]);
                float4 wb = *reinterpret_cast<float4*>(&sw[1][k][cl]);
                s00 += u0*wa.x; s01 += u1*wb.x; s02 += u2*wb.x; s03 += u3*wb.x;
                s10 += u0*wa.y; s11 += u1*wb.y; s12 += u2*wb.y; s13 += u3*wb.y;
                s20 += u0*wa.z; s21 += u1*wb.z; s22 += u2*wb.z; s23 += u3*wb.z;
                s30 += u0*wa.w; s31 += u1*wb.w; s32 += u2*wb.w; s33 += u3*wb.w;
            }
            if (valid) {
                int mm = m0 + m;
                g_uw3s[(e*Cc + c0 + cl + 0)*NM3 + mm] = make_float4(s00,s01,s02,s03);
                g_uw3s[(e*Cc + c0 + cl + 1)*NM3 + mm] = make_float4(s10,s11,s12,s13);
                g_uw3s[(e*Cc + c0 + cl + 2)*NM3 + mm] = make_float4(s20,s21,s22,s23);
                g_uw3s[(e*Cc + c0 + cl + 3)*NM3 + mm] = make_float4(s30,s31,s32,s33);
            }
        }
    } else if (blk < F3_BLKS + F2_BLKS) {
        int tid = (blk - F3_BLKS)*256 + t;
        int m = tid % NM2; int ec = tid / NM2;
        int c = ec % Cc;   int e  = ec / Cc;
        const float* w0  = w2 + ((0*Ss + e)*NK2)*Cc + c;
        const float* w1v = w2 + ((1*Ss + e)*NK2)*Cc + c;
        float s0=0.f, s1=0.f, s2=0.f, s3=0.f;
        #pragma unroll
        for (int k = 0; k < NK2; k++) {
            float a = __ldg(w0 + k*Cc), b = __ldg(w1v + k*Cc);   // warp-uniform
            s0 += g_u2s[(0*NK2 + k)*NM2 + m]*a;
            s1 += g_u2s[(1*NK2 + k)*NM2 + m]*b;
            s2 += g_u2s[(2*NK2 + k)*NM2 + m]*b;
            s3 += g_u2s[(3*NK2 + k)*NM2 + m]*b;
        }
        g_uw2s[tid] = make_float4(s0,s1,s2,s3);
    } else {
        int tid = (blk - F3_BLKS - F2_BLKS)*256 + t;
        int i = tid % Dd; int ec = tid / Dd;
        int c = ec % Cc;  int e  = ec / Cc;
        float s[OT];
        #pragma unroll
        for (int o = 0; o < OT; o++) {
            int set = (o == 0) ? 0 : 1;
            float acc = 0.f;
            #pragma unroll
            for (int k = 0; k < NK1; k++) {
                float uv = (o == 0) ? u1_0[i*NK1 + k]
                                    : u1_1[(((o-1)*Dd) + i)*NK1 + k];
                acc += uv * w1[((set*Ss + e)*NK1 + k)*Cc + c];
            }
            s[o] = acc;
        }
        g_uw1s[tid] = make_float4(s[0], s[1], s[2], s[3]);
    }
}

// ---------------- main symmetric-contraction kernel: 2 nodes/thread, balanced ----------------
#define FMA2(acc, a, b) asm("fma.rn.f32x2 %0, %1, %2, %0;" : "+l"(acc) : "l"(a), "l"(b))
#define MUL2(d, a, b)   asm("mul.rn.f32x2 %0, %1, %2;" : "=l"(d) : "l"(a), "l"(b))

// Grid (Cc, 4): CTA = (channel c, global position range [256q, 256q+256)).
// Ranges are species-segmented; basis reloaded per segment (<=2 typical).
// Thread handles 2 nodes (t and t+128 within the segment chunk).
__global__ void __launch_bounds__(128) k_main(const float* __restrict__ nf) {
    __shared__ ulonglong2 su3[NM3];     // 13056 B
    __shared__ ulonglong2 su2[NM2];     //  2176 B
    __shared__ ulonglong2 su1[Dd];      //   256 B
    int c = blockIdx.x, q = blockIdx.y;
    int t = threadIdx.x;
    int lo = q*256, hi = lo + 256;      // Bn = 1024 = 4*256 exactly
    int offe = 0;
    for (int e = 0; e < Ss; e++) {
        int ne = g_count[e];
        int slo = lo > offe ? lo : offe;
        int shi = hi < offe + ne ? hi : offe + ne;
        offe += ne;
        if (slo >= shi) continue;                  // uniform across block
        int ec = e*Cc + c;
        const ulonglong2* G3 = reinterpret_cast<const ulonglong2*>(g_uw3s) + ec*NM3;
        const ulonglong2* G2 = reinterpret_cast<const ulonglong2*>(g_uw2s) + ec*NM2;
        const ulonglong2* G1 = reinterpret_cast<const ulonglong2*>(g_uw1s) + ec*Dd;
        __syncthreads();                           // close previous segment's reads
        for (int idx = t; idx < NM3; idx += 128) su3[idx] = G3[idx];
        for (int idx = t; idx < NM2; idx += 128) su2[idx] = G2[idx];
        if (t < Dd) su1[t] = G1[t];
        __syncthreads();
        for (int base = slo; base < shi; base += 256) {
            int pa = base + t;
            if (pa >= shi) continue;               // whole pair invalid
            int pb = pa + 128;
            bool vb = pb < shi;
            int ba = g_pb[pa];
            const float4* srcA = reinterpret_cast<const float4*>(nf + (ba*Cc + c)*Dd);
            float4 a0 = srcA[0], a1 = srcA[1], a2 = srcA[2], a3 = srcA[3];
            float xa[16] = {a0.x,a0.y,a0.z,a0.w, a1.x,a1.y,a1.z,a1.w,
                            a2.x,a2.y,a2.z,a2.w, a3.x,a3.y,a3.z,a3.w};
            float xbv[16];
            if (vb) {
                int bb = g_pb[pb];
                const float4* srcB = reinterpret_cast<const float4*>(nf + (bb*Cc + c)*Dd);
                float4 b0 = srcB[0], b1 = srcB[1], b2 = srcB[2], b3 = srcB[3];
                xbv[0]=b0.x; xbv[1]=b0.y; xbv[2]=b0.z; xbv[3]=b0.w;
                xbv[4]=b1.x; xbv[5]=b1.y; xbv[6]=b1.z; xbv[7]=b1.w;
                xbv[8]=b2.x; xbv[9]=b2.y; xbv[10]=b2.z; xbv[11]=b2.w;
                xbv[12]=b3.x; xbv[13]=b3.y; xbv[14]=b3.z; xbv[15]=b3.w;
            } else {
                #pragma unroll
                for (int i = 0; i < 16; i++) xbv[i] = xa[i];   // duplicate (not stored)
            }
            u64 xd[16], yd[16];
            #pragma unroll
            for (int i = 0; i < 16; i++) {
                unsigned ua = __float_as_uint(xa[i]);
                unsigned ub = __float_as_uint(xbv[i]);
                asm("mov.b64 %0, {%1, %1};" : "=l"(xd[i]) : "r"(ua));
                asm("mov.b64 %0, {%1, %1};" : "=l"(yd[i]) : "r"(ub));
            }
            u64 aA01 = 0ull, aA23 = 0ull, aB01 = 0ull, aB23 = 0ull;
            int m3 = 0, m2 = 0;
            #pragma unroll
            for (int j = 0; j < 16; j++) {
                u64 xj = xd[j], yj = yd[j];
                ulonglong2 u1r = su1[j];
                FMA2(aA01, u1r.x, xj); FMA2(aA23, u1r.y, xj);
                FMA2(aB01, u1r.x, yj); FMA2(aB23, u1r.y, yj);
                const int w = 16 - j;
                #pragma unroll 1
                for (int i = 0; i <= j; i++) {
                    u64 xxA; MUL2(xxA, xd[i], xj);
                    u64 xxB; MUL2(xxB, yd[i], yj);
                    ulonglong2 u2r = su2[m2 + i];
                    u64 dA01 = u2r.x, dA23 = u2r.y;
                    u64 dB01 = u2r.x, dB23 = u2r.y;
                    const ulonglong2* s3 = &su3[m3 + i*w];
                    #pragma unroll
                    for (int l = j; l < 16; l++) {
                        ulonglong2 u = s3[l - j];            // LDS.128 broadcast
                        FMA2(dA01, u.x, xd[l]); FMA2(dA23, u.y, xd[l]);
                        FMA2(dB01, u.x, yd[l]); FMA2(dB23, u.y, yd[l]);
                    }
                    FMA2(aA01, xxA, dA01); FMA2(aA23, xxA, dA23);
                    FMA2(aB01, xxB, dB01); FMA2(aB23, xxB, dB23);
                }
                m2 += j + 1;
                m3 += (j + 1) * w;
            }
            unsigned r0, r1, r2, r3;
            asm("mov.b64 {%0,%1}, %2;" : "=r"(r0), "=r"(r1) : "l"(aA01));
            asm("mov.b64 {%0,%1}, %2;" : "=r"(r2), "=r"(r3) : "l"(aA23));
            g_Y[(0*Cc + c)*Bn + pa] = __uint_as_float(r0);
            g_Y[(1*Cc + c)*Bn + pa] = __uint_as_float(r1);
            g_Y[(2*Cc + c)*Bn + pa] = __uint_as_float(r2);
            g_Y[(3*Cc + c)*Bn + pa] = __uint_as_float(r3);
            if (vb) {
                unsigned s0, s1, s2, s3v;
                asm("mov.b64 {%0,%1}, %2;" : "=r"(s0), "=r"(s1) : "l"(aB01));
                asm("mov.b64 {%0,%1}, %2;" : "=r"(s2), "=r"(s3v) : "l"(aB23));
                g_Y[(0*Cc + c)*Bn + pb] = __uint_as_float(s0);
                g_Y[(1*Cc + c)*Bn + pb] = __uint_as_float(s1);
                g_Y[(2*Cc + c)*Bn + pb] = __uint_as_float(s2);
                g_Y[(3*Cc + c)*Bn + pb] = __uint_as_float(s3v);
            }
        }
    }
}

// ---------------- final equivariant linear (R7-exact: one wave, 512 thr) ----------------
#define LIN_SMEM (Cc*Cc*4 + Cc*32*4)   // Ws 64KB + Ys 16KB = 81920 B
__global__ void __launch_bounds__(512) k_linear(const float* __restrict__ wlin,
                                                float* __restrict__ out) {
    extern __shared__ float sm[];
    float* Ws = sm;              // [128][128]
    float* Ys = sm + Cc*Cc;      // [128][32]
    int o  = blockIdx.y;
    int p0 = blockIdx.x * 32;
    int set = (o == 0) ? 0 : 1;
    int t  = threadIdx.x;
    const float4* wsrc = reinterpret_cast<const float4*>(wlin + set*Cc*Cc);
    float4* wdst = reinterpret_cast<float4*>(Ws);
    #pragma unroll
    for (int idx = t; idx < Cc*Cc/4; idx += 512) wdst[idx] = wsrc[idx];
    #pragma unroll
    for (int idx = t; idx < Cc*32; idx += 512) {
        int cc = idx >> 5, pp = idx & 31;
        Ys[cc*32 + pp] = g_Y[(o*Cc + cc)*Bn + p0 + pp];
    }
    __syncthreads();
    int tp = t & 15;          // 16 row-slots x 2 rows = 32
    int tn = t >> 4;          // 32 col-slots x 4 cols = 128
    float a0x=0,a0y=0,a0z=0,a0w=0, a1x=0,a1y=0,a1z=0,a1w=0;
    #pragma unroll 16
    for (int cc = 0; cc < Cc; cc++) {
        float2 y = *reinterpret_cast<const float2*>(&Ys[cc*32 + tp*2]);   // broadcast-dedup
        float4 w = *reinterpret_cast<const float4*>(&Ws[cc*Cc + tn*4]);   // broadcast-dedup
        a0x += y.x*w.x; a0y += y.x*w.y; a0z += y.x*w.z; a0w += y.x*w.w;
        a1x += y.y*w.x; a1y += y.y*w.y; a1z += y.y*w.z; a1w += y.y*w.w;
    }
    const float scale = 0.08838834764831845f;    // 1/sqrt(128)
    float4 r0 = make_float4(a0x*scale, a0y*scale, a0z*scale, a0w*scale);
    float4 r1 = make_float4(a1x*scale, a1y*scale, a1z*scale, a1w*scale);
    int p_a = p0 + tp*2;
    int b0 = g_pb[p_a + 0], b1 = g_pb[p_a + 1];
    if (o == 0) {
        *reinterpret_cast<float4*>(&out[b0*512 + tn*4]) = r0;
        *reinterpret_cast<float4*>(&out[b1*512 + tn*4]) = r1;
    } else {
        int op = o - 1;
        float* o0 = &out[b0*512 + 128 + op];
        float* o1 = &out[b1*512 + 128 + op];
        o0[(tn*4+0)*3] = r0.x; o0[(tn*4+1)*3] = r0.y; o0[(tn*4+2)*3] = r0.z; o0[(tn*4+3)*3] = r0.w;
        o1[(tn*4+0)*3] = r1.x; o1[(tn*4+1)*3] = r1.y; o1[(tn*4+2)*3] = r1.z; o1[(tn*4+3)*3] = r1.w;
    }
}

// ---------------- launch (4 launches) ----------------
extern "C" void kernel_launch(void* const* d_in, const int* in_sizes, int n_in,
                              void* d_out, int out_size) {
    const float* nf   = (const float*)d_in[0];
    const float* u3_0 = (const float*)d_in[1];
    const float* u3_1 = (const float*)d_in[2];
    const float* u2_0 = (const float*)d_in[3];
    const float* u2_1 = (const float*)d_in[4];
    const float* u1_0 = (const float*)d_in[5];
    const float* u1_1 = (const float*)d_in[6];
    const float* w3   = (const float*)d_in[7];
    const float* w2   = (const float*)d_in[8];
    const float* w1   = (const float*)d_in[9];
    const float* wl   = (const float*)d_in[10];
    const int*   sp   = (const int*)d_in[11];
    float* out = (float*)d_out;

    cudaFuncSetAttribute(k_linear, cudaFuncAttributeMaxDynamicSharedMemorySize, LIN_SMEM);

    k_prep<<<1 + SYM3_BLKS + 4, 256>>>(sp, u3_0, u3_1, u2_0, u2_1);
    k_fold<<<F3_BLKS + F2_BLKS + F1_BLKS, 256>>>(w3, w2, u1_0, u1_1, w1);
    k_main<<<dim3(Cc, 4), 128>>>(nf);
    k_linear<<<dim3(Bn/32, 4), 512, LIN_SMEM>>>(wl, out);
}